// round 1
// baseline (speedup 1.0000x reference)
#include <cuda_runtime.h>

#define NCH   256
#define FH    50
#define FW    50
#define NPROP 1024
#define OUTS  7
#define SRATE 2
#define NS    14          // OUTS*SRATE
#define BINS  49
#define OUT_PER_PROP (NCH*BINS)   // 12544
#define PITCH 257         // odd -> conflict-free smem transpose staging

// fm transposed to [y][x][c] so channel gathers are coalesced
__device__ float g_fmT[FH * FW * NCH];

// ---------------- Kernel 1: (C,H,W) -> (H,W,C) transpose ----------------
__global__ void transpose_kernel(const float* __restrict__ fm) {
    __shared__ float tile[32][33];
    const int P = FH * FW;               // 2500
    int pTile = blockIdx.x * 32;
    int cTile = blockIdx.y * 32;
    int tx = threadIdx.x, ty = threadIdx.y;

    int p = pTile + tx;
    #pragma unroll
    for (int i = 0; i < 32; i += 8) {
        int c = cTile + ty + i;
        if (p < P) tile[ty + i][tx] = fm[c * P + p];
    }
    __syncthreads();
    int c2 = cTile + tx;
    #pragma unroll
    for (int i = 0; i < 32; i += 8) {
        int pp = pTile + ty + i;
        if (pp < P) g_fmT[pp * NCH + c2] = tile[tx][ty + i];
    }
}

// ---------------- Kernel 2: ROI Align, one proposal per block ----------------
__global__ __launch_bounds__(128) void roialign_kernel(
    const float* __restrict__ proposals, float* __restrict__ out)
{
    const int n = blockIdx.x;
    const int t = threadIdx.x;           // 0..127

    __shared__ int   sx0[NS], sx1[NS], sy0[NS], sy1[NS];
    __shared__ float swx0[NS], swx1[NS], swy0[NS], swy1[NS];
    __shared__ float WX[OUTS][4], WY[OUTS][4];
    extern __shared__ float stage[];     // BINS * PITCH floats

    // ---- per-axis per-sample interpolation tables (28 threads) ----
    if (t < 2 * NS) {
        const int axis = t / NS;         // 0 = x, 1 = y
        const int s    = t % NS;
        const float SC = 1.0f / 16.0f;
        float lo = proposals[n * 4 + (axis == 0 ? 0 : 1)] * SC * SC;
        float hi = proposals[n * 4 + (axis == 0 ? 2 : 3)] * SC * SC;
        float roi   = fmaxf(hi - lo, 1.0f);
        float binsz = roi * (1.0f / OUTS);
        float gv    = ((float)s + 0.5f) * 0.5f;
        float v     = lo + binsz * gv;
        const float Lf = 50.0f;
        bool valid = (v >= -1.0f) && (v <= Lf);
        float vc = fminf(fmaxf(v, 0.0f), Lf - 1.0f);
        int i0 = min((int)floorf(vc), 49);
        int i1 = min(i0 + 1, 49);
        float l = vc - (float)i0;
        float h = 1.0f - l;
        if (!valid) { h = 0.0f; l = 0.0f; }
        if (axis == 0) { sx0[s] = i0; sx1[s] = i1; swx0[s] = h; swx1[s] = l; }
        else           { sy0[s] = i0; sy1[s] = i1; swy0[s] = h; swy1[s] = l; }
    }
    __syncthreads();

    const int xb = sx0[0], yb = sy0[0];
    const int xspan = sx1[NS - 1] - xb;
    const int yspan = sy1[NS - 1] - yb;
    const bool fast = (xspan <= 2) && (yspan <= 2);

    // ---- aggregate bin weights WX/WY (14 threads); fast path only ----
    if (t < 2 * OUTS) {
        const int axis = t / OUTS;
        const int b    = t % OUTS;
        float w0 = 0.f, w1 = 0.f, w2 = 0.f;
        #pragma unroll
        for (int d = 0; d < 2; d++) {
            int s = 2 * b + d;
            int r0, r1; float a, c;
            if (axis == 0) { r0 = sx0[s] - xb; r1 = sx1[s] - xb; a = swx0[s]; c = swx1[s]; }
            else           { r0 = sy0[s] - yb; r1 = sy1[s] - yb; a = swy0[s]; c = swy1[s]; }
            if ((unsigned)r0 < 3u) { if (r0 == 0) w0 += a; else if (r0 == 1) w1 += a; else w2 += a; }
            if ((unsigned)r1 < 3u) { if (r1 == 0) w0 += c; else if (r1 == 1) w1 += c; else w2 += c; }
        }
        if (axis == 0) { WX[b][0] = w0; WX[b][1] = w1; WX[b][2] = w2; }
        else           { WY[b][0] = w0; WY[b][1] = w1; WY[b][2] = w2; }
    }
    __syncthreads();

    const int c0 = t;            // channels t and t+128 (bank-friendly scatter)
    const int c1 = t + 128;

    if (fast) {
        // 3x3 texel block cached in registers, all 49 bins from registers
        float b0[3][3], b1[3][3];
        #pragma unroll
        for (int ty = 0; ty < 3; ty++) {
            int yy = min(yb + ty, FH - 1);
            #pragma unroll
            for (int tx = 0; tx < 3; tx++) {
                int xx = min(xb + tx, FW - 1);
                const float* p = &g_fmT[(yy * FW + xx) * NCH];
                b0[ty][tx] = p[c0];
                b1[ty][tx] = p[c1];
            }
        }
        #pragma unroll
        for (int by = 0; by < OUTS; by++) {
            float wy0 = WY[by][0], wy1 = WY[by][1], wy2 = WY[by][2];
            float t0[3], t1[3];
            #pragma unroll
            for (int tx = 0; tx < 3; tx++) {
                t0[tx] = wy0 * b0[0][tx] + wy1 * b0[1][tx] + wy2 * b0[2][tx];
                t1[tx] = wy0 * b1[0][tx] + wy1 * b1[1][tx] + wy2 * b1[2][tx];
            }
            #pragma unroll
            for (int bx = 0; bx < OUTS; bx++) {
                float wx0 = WX[bx][0], wx1 = WX[bx][1], wx2 = WX[bx][2];
                float v0 = 0.25f * (wx0 * t0[0] + wx1 * t0[1] + wx2 * t0[2]);
                float v1 = 0.25f * (wx0 * t1[0] + wx1 * t1[1] + wx2 * t1[2]);
                int j = by * OUTS + bx;
                stage[j * PITCH + c0] = v0;
                stage[j * PITCH + c1] = v1;
            }
        }
    } else {
        // general fallback: literal per-sample bilinear gather
        for (int j = 0; j < BINS; j++) {
            int by = j / OUTS, bx = j - by * OUTS;
            float a0 = 0.f, a1 = 0.f;
            #pragma unroll
            for (int dy = 0; dy < 2; dy++) {
                int sy = 2 * by + dy;
                const float* r0 = &g_fmT[sy0[sy] * FW * NCH];
                const float* r1 = &g_fmT[sy1[sy] * FW * NCH];
                float hy = swy0[sy], ly = swy1[sy];
                #pragma unroll
                for (int dx = 0; dx < 2; dx++) {
                    int sx = 2 * bx + dx;
                    int o0 = sx0[sx] * NCH, o1 = sx1[sx] * NCH;
                    float hx = swx0[sx], lx = swx1[sx];
                    a0 += hy * (hx * r0[o0 + c0] + lx * r0[o1 + c0])
                        + ly * (hx * r1[o0 + c0] + lx * r1[o1 + c0]);
                    a1 += hy * (hx * r0[o0 + c1] + lx * r0[o1 + c1])
                        + ly * (hx * r1[o0 + c1] + lx * r1[o1 + c1]);
                }
            }
            stage[j * PITCH + c0] = 0.25f * a0;
            stage[j * PITCH + c1] = 0.25f * a1;
        }
    }
    __syncthreads();

    // ---- coalesced linear writeback: out[n][c][j] ----
    float* outp = out + (size_t)n * OUT_PER_PROP;
    for (int i = t; i < OUT_PER_PROP; i += 128) {
        int c = i / BINS;
        int j = i - c * BINS;
        outp[i] = stage[j * PITCH + c];
    }
}

extern "C" void kernel_launch(void* const* d_in, const int* in_sizes, int n_in,
                              void* d_out, int out_size) {
    const float* fm        = (const float*)d_in[0];
    const float* proposals = (const float*)d_in[1];
    float* out = (float*)d_out;

    static bool attr_set = false;
    const int stage_bytes = BINS * PITCH * (int)sizeof(float);  // 50372
    if (!attr_set) {
        cudaFuncSetAttribute(roialign_kernel,
                             cudaFuncAttributeMaxDynamicSharedMemorySize,
                             stage_bytes);
        attr_set = true;
    }

    transpose_kernel<<<dim3((FH * FW + 31) / 32, NCH / 32), dim3(32, 8)>>>(fm);
    roialign_kernel<<<NPROP, 128, stage_bytes>>>(proposals, out);
}

// round 4
// speedup vs baseline: 1.1070x; 1.1070x over previous
#include <cuda_runtime.h>

#define NCH   256
#define FH    50
#define FW    50
#define NPROP 1024
#define OUTS  7
#define NS    14          // OUTS*SRATE
#define BINS  49
#define HALF  128         // channels per staging pass
#define HALF_ELEMS (HALF*BINS)    // 6272
#define OUT_PER_PROP (NCH*BINS)   // 12544
#define PITCH 129         // 129 % 32 == 1 -> conflict-free stage both directions

// fm transposed to [y][x][c] so channel gathers are coalesced
__device__ float g_fmT[FH * FW * NCH];

// ---------------- Kernel 1: (C,H,W) -> (H,W,C) transpose ----------------
__global__ void transpose_kernel(const float* __restrict__ fm) {
    __shared__ float tile[32][33];
    const int P = FH * FW;               // 2500
    int pTile = blockIdx.x * 32;
    int cTile = blockIdx.y * 32;
    int tx = threadIdx.x, ty = threadIdx.y;

    int p = pTile + tx;
    #pragma unroll
    for (int i = 0; i < 32; i += 8) {
        int c = cTile + ty + i;
        if (p < P) tile[ty + i][tx] = fm[c * P + p];
    }
    __syncthreads();
    int c2 = cTile + tx;
    #pragma unroll
    for (int i = 0; i < 32; i += 8) {
        int pp = pTile + ty + i;
        if (pp < P) g_fmT[pp * NCH + c2] = tile[tx][ty + i];
    }
}

// ---------------- Kernel 2: ROI Align, one proposal per block ----------------
__global__ __launch_bounds__(128) void roialign_kernel(
    const float* __restrict__ proposals, float* __restrict__ out)
{
    const int n = blockIdx.x;
    const int t = threadIdx.x;           // 0..127

    __shared__ int   sx0[NS], sx1[NS], sy0[NS], sy1[NS];
    __shared__ float swx0[NS], swx1[NS], swy0[NS], swy1[NS];
    __shared__ float WX[OUTS][4], WY[OUTS][4];
    __shared__ float stage[BINS * PITCH];      // 25,284 B -> 8 blocks/SM

    // ---- per-axis per-sample interpolation tables (28 threads) ----
    if (t < 2 * NS) {
        const int axis = t / NS;         // 0 = x, 1 = y
        const int s    = t % NS;
        const float SC = 1.0f / 16.0f;
        float lo = proposals[n * 4 + (axis == 0 ? 0 : 1)] * SC * SC;
        float hi = proposals[n * 4 + (axis == 0 ? 2 : 3)] * SC * SC;
        float roi   = fmaxf(hi - lo, 1.0f);
        float binsz = roi * (1.0f / OUTS);
        float gv    = ((float)s + 0.5f) * 0.5f;
        float v     = lo + binsz * gv;
        const float Lf = 50.0f;
        bool valid = (v >= -1.0f) && (v <= Lf);
        float vc = fminf(fmaxf(v, 0.0f), Lf - 1.0f);
        int i0 = min((int)floorf(vc), 49);
        int i1 = min(i0 + 1, 49);
        float l = vc - (float)i0;
        float h = 1.0f - l;
        if (!valid) { h = 0.0f; l = 0.0f; }
        if (axis == 0) { sx0[s] = i0; sx1[s] = i1; swx0[s] = h; swx1[s] = l; }
        else           { sy0[s] = i0; sy1[s] = i1; swy0[s] = h; swy1[s] = l; }
    }
    __syncthreads();

    const int xb = sx0[0], yb = sy0[0];
    const int xspan = sx1[NS - 1] - xb;
    const int yspan = sy1[NS - 1] - yb;
    const bool fast = (xspan <= 2) && (yspan <= 2);

    // ---- aggregate bin weights WX/WY (14 threads); 0.25 bin-avg folded in ----
    if (t < 2 * OUTS) {
        const int axis = t / OUTS;
        const int b    = t % OUTS;
        float w0 = 0.f, w1 = 0.f, w2 = 0.f;
        #pragma unroll
        for (int d = 0; d < 2; d++) {
            int s = 2 * b + d;
            int r0, r1; float a, c;
            if (axis == 0) { r0 = sx0[s] - xb; r1 = sx1[s] - xb; a = swx0[s]; c = swx1[s]; }
            else           { r0 = sy0[s] - yb; r1 = sy1[s] - yb; a = swy0[s]; c = swy1[s]; }
            if ((unsigned)r0 < 3u) { if (r0 == 0) w0 += a; else if (r0 == 1) w1 += a; else w2 += a; }
            if ((unsigned)r1 < 3u) { if (r1 == 0) w0 += c; else if (r1 == 1) w1 += c; else w2 += c; }
        }
        const float q = 0.5f;            // 0.5*0.5 = 0.25 bin average
        if (axis == 0) { WX[b][0] = w0*q; WX[b][1] = w1*q; WX[b][2] = w2*q; }
        else           { WY[b][0] = w0*q; WY[b][1] = w1*q; WY[b][2] = w2*q; }
    }
    __syncthreads();

    // starting (channel, bin) for the strength-reduced drain loop
    const int cc_start = t / BINS;       // 0..2
    const int j_start  = t - cc_start * BINS;

    // ---- two staging passes of 128 channels each ----
    #pragma unroll
    for (int half = 0; half < 2; half++) {
        const int c = t + half * HALF;

        if (fast) {
            float b9[3][3];
            #pragma unroll
            for (int ty = 0; ty < 3; ty++) {
                int yy = min(yb + ty, FH - 1);
                #pragma unroll
                for (int tx = 0; tx < 3; tx++) {
                    int xx = min(xb + tx, FW - 1);
                    b9[ty][tx] = g_fmT[(yy * FW + xx) * NCH + c];
                }
            }
            #pragma unroll
            for (int by = 0; by < OUTS; by++) {
                float wy0 = WY[by][0], wy1 = WY[by][1], wy2 = WY[by][2];
                float t0 = wy0 * b9[0][0] + wy1 * b9[1][0] + wy2 * b9[2][0];
                float t1 = wy0 * b9[0][1] + wy1 * b9[1][1] + wy2 * b9[2][1];
                float t2 = wy0 * b9[0][2] + wy1 * b9[1][2] + wy2 * b9[2][2];
                #pragma unroll
                for (int bx = 0; bx < OUTS; bx++) {
                    float v = WX[bx][0] * t0 + WX[bx][1] * t1 + WX[bx][2] * t2;
                    stage[(by * OUTS + bx) * PITCH + t] = v;
                }
            }
        } else {
            // general fallback: literal per-sample bilinear gather
            for (int j = 0; j < BINS; j++) {
                int by = j / OUTS, bx = j - by * OUTS;
                float a0 = 0.f;
                #pragma unroll
                for (int dy = 0; dy < 2; dy++) {
                    int sy = 2 * by + dy;
                    const float* r0 = &g_fmT[sy0[sy] * FW * NCH];
                    const float* r1 = &g_fmT[sy1[sy] * FW * NCH];
                    float hy = swy0[sy], ly = swy1[sy];
                    #pragma unroll
                    for (int dx = 0; dx < 2; dx++) {
                        int sx = 2 * bx + dx;
                        int o0 = sx0[sx] * NCH, o1 = sx1[sx] * NCH;
                        float hx = swx0[sx], lx = swx1[sx];
                        a0 += hy * (hx * r0[o0 + c] + lx * r0[o1 + c])
                            + ly * (hx * r1[o0 + c] + lx * r1[o1 + c]);
                    }
                }
                stage[j * PITCH + t] = 0.25f * a0;
            }
        }
        __syncthreads();

        // ---- coalesced linear writeback for this half (strength-reduced) ----
        float* outp = out + (size_t)n * OUT_PER_PROP + (size_t)half * HALF_ELEMS;
        int cc = cc_start, j = j_start;
        #pragma unroll 4
        for (int i = t; i < HALF_ELEMS; i += 128) {
            outp[i] = stage[j * PITCH + cc];
            // advance (cc, j) by 128 elements: 128 = 2*49 + 30
            cc += 2; j += 30;
            if (j >= BINS) { j -= BINS; cc += 1; }
        }
        __syncthreads();
    }
}

extern "C" void kernel_launch(void* const* d_in, const int* in_sizes, int n_in,
                              void* d_out, int out_size) {
    const float* fm        = (const float*)d_in[0];
    const float* proposals = (const float*)d_in[1];
    float* out = (float*)d_out;

    transpose_kernel<<<dim3((FH * FW + 31) / 32, NCH / 32), dim3(32, 8)>>>(fm);
    roialign_kernel<<<NPROP, 128>>>(proposals, out);
}

// round 5
// speedup vs baseline: 1.1494x; 1.0383x over previous
#include <cuda_runtime.h>

#define NCH   256
#define FH    50
#define FW    50
#define NPROP 1024
#define OUTS  7
#define NS    14          // OUTS*SRATE
#define BINS  49
#define HALF  128         // channels per block
#define HALF_ELEMS (HALF*BINS)    // 6272
#define OUT_PER_PROP (NCH*BINS)   // 12544
#define PITCH 129         // 129 % 32 == 1 -> conflict-free stage both directions

// fm transposed to [y][x][c] so channel gathers are coalesced
__device__ float g_fmT[FH * FW * NCH];

// ---------------- Kernel 1: (C,H,W) -> (H,W,C) transpose ----------------
__global__ void transpose_kernel(const float* __restrict__ fm) {
    __shared__ float tile[32][33];
    const int P = FH * FW;               // 2500
    int pTile = blockIdx.x * 32;
    int cTile = blockIdx.y * 32;
    int tx = threadIdx.x, ty = threadIdx.y;

    int p = pTile + tx;
    #pragma unroll
    for (int i = 0; i < 32; i += 8) {
        int c = cTile + ty + i;
        if (p < P) tile[ty + i][tx] = fm[c * P + p];
    }
    __syncthreads();
    int c2 = cTile + tx;
    #pragma unroll
    for (int i = 0; i < 32; i += 8) {
        int pp = pTile + ty + i;
        if (pp < P) g_fmT[pp * NCH + c2] = tile[tx][ty + i];
    }
}

// -------- Kernel 2: ROI Align, one (proposal, channel-half) per block --------
__global__ __launch_bounds__(128) void roialign_kernel(
    const float* __restrict__ proposals, float* __restrict__ out)
{
    const int n    = blockIdx.x >> 1;
    const int half = blockIdx.x & 1;
    const int t    = threadIdx.x;        // 0..127

    __shared__ int   sx0[NS], sx1[NS], sy0[NS], sy1[NS];
    __shared__ float swx0[NS], swx1[NS], swy0[NS], swy1[NS];
    __shared__ float WX[OUTS][4], WY[OUTS][4];
    __shared__ float stage[BINS * PITCH];      // 25,284 B -> 8 blocks/SM

    // ---- per-axis per-sample interpolation tables (28 threads) ----
    if (t < 2 * NS) {
        const int axis = t / NS;         // 0 = x, 1 = y
        const int s    = t % NS;
        const float SC = 1.0f / 16.0f;
        float lo = proposals[n * 4 + (axis == 0 ? 0 : 1)] * SC * SC;
        float hi = proposals[n * 4 + (axis == 0 ? 2 : 3)] * SC * SC;
        float roi   = fmaxf(hi - lo, 1.0f);
        float binsz = roi * (1.0f / OUTS);
        float gv    = ((float)s + 0.5f) * 0.5f;
        float v     = lo + binsz * gv;
        const float Lf = 50.0f;
        bool valid = (v >= -1.0f) && (v <= Lf);
        float vc = fminf(fmaxf(v, 0.0f), Lf - 1.0f);
        int i0 = min((int)floorf(vc), 49);
        int i1 = min(i0 + 1, 49);
        float l = vc - (float)i0;
        float h = 1.0f - l;
        if (!valid) { h = 0.0f; l = 0.0f; }
        if (axis == 0) { sx0[s] = i0; sx1[s] = i1; swx0[s] = h; swx1[s] = l; }
        else           { sy0[s] = i0; sy1[s] = i1; swy0[s] = h; swy1[s] = l; }
    }
    __syncthreads();

    const int xb = sx0[0], yb = sy0[0];
    const int xspan = sx1[NS - 1] - xb;
    const int yspan = sy1[NS - 1] - yb;
    const bool fast = (xspan <= 2) && (yspan <= 2);

    // ---- aggregate bin weights WX/WY (14 threads); 0.25 bin-avg folded in ----
    if (t < 2 * OUTS) {
        const int axis = t / OUTS;
        const int b    = t % OUTS;
        float w0 = 0.f, w1 = 0.f, w2 = 0.f;
        #pragma unroll
        for (int d = 0; d < 2; d++) {
            int s = 2 * b + d;
            int r0, r1; float a, c;
            if (axis == 0) { r0 = sx0[s] - xb; r1 = sx1[s] - xb; a = swx0[s]; c = swx1[s]; }
            else           { r0 = sy0[s] - yb; r1 = sy1[s] - yb; a = swy0[s]; c = swy1[s]; }
            if ((unsigned)r0 < 3u) { if (r0 == 0) w0 += a; else if (r0 == 1) w1 += a; else w2 += a; }
            if ((unsigned)r1 < 3u) { if (r1 == 0) w0 += c; else if (r1 == 1) w1 += c; else w2 += c; }
        }
        const float q = 0.5f;            // 0.5*0.5 = 0.25 bin average
        if (axis == 0) { WX[b][0] = w0*q; WX[b][1] = w1*q; WX[b][2] = w2*q; }
        else           { WY[b][0] = w0*q; WY[b][1] = w1*q; WY[b][2] = w2*q; }
    }
    __syncthreads();

    const int c = t + half * HALF;       // this block's channel

    if (fast) {
        float b9[3][3];
        #pragma unroll
        for (int ty = 0; ty < 3; ty++) {
            int yy = min(yb + ty, FH - 1);
            #pragma unroll
            for (int tx = 0; tx < 3; tx++) {
                int xx = min(xb + tx, FW - 1);
                b9[ty][tx] = g_fmT[(yy * FW + xx) * NCH + c];
            }
        }
        #pragma unroll
        for (int by = 0; by < OUTS; by++) {
            float wy0 = WY[by][0], wy1 = WY[by][1], wy2 = WY[by][2];
            float t0 = wy0 * b9[0][0] + wy1 * b9[1][0] + wy2 * b9[2][0];
            float t1 = wy0 * b9[0][1] + wy1 * b9[1][1] + wy2 * b9[2][1];
            float t2 = wy0 * b9[0][2] + wy1 * b9[1][2] + wy2 * b9[2][2];
            #pragma unroll
            for (int bx = 0; bx < OUTS; bx++) {
                float v = WX[bx][0] * t0 + WX[bx][1] * t1 + WX[bx][2] * t2;
                stage[(by * OUTS + bx) * PITCH + t] = v;
            }
        }
    } else {
        // general fallback: literal per-sample bilinear gather
        for (int j = 0; j < BINS; j++) {
            int by = j / OUTS, bx = j - by * OUTS;
            float a0 = 0.f;
            #pragma unroll
            for (int dy = 0; dy < 2; dy++) {
                int sy = 2 * by + dy;
                const float* r0 = &g_fmT[sy0[sy] * FW * NCH];
                const float* r1 = &g_fmT[sy1[sy] * FW * NCH];
                float hy = swy0[sy], ly = swy1[sy];
                #pragma unroll
                for (int dx = 0; dx < 2; dx++) {
                    int sx = 2 * bx + dx;
                    int o0 = sx0[sx] * NCH, o1 = sx1[sx] * NCH;
                    float hx = swx0[sx], lx = swx1[sx];
                    a0 += hy * (hx * r0[o0 + c] + lx * r0[o1 + c])
                        + ly * (hx * r1[o0 + c] + lx * r1[o1 + c]);
                }
            }
            stage[j * PITCH + t] = 0.25f * a0;
        }
    }
    __syncthreads();

    // ---- coalesced linear writeback (strength-reduced, 49 iters, no tail) ----
    float* outp = out + (size_t)n * OUT_PER_PROP + (size_t)half * HALF_ELEMS;
    int cc = t / BINS;                   // 0..2
    int j  = t - cc * BINS;
    #pragma unroll 7
    for (int i = t; i < HALF_ELEMS; i += 128) {
        outp[i] = stage[j * PITCH + cc];
        // advance (cc, j) by 128 elements: 128 = 2*49 + 30
        cc += 2; j += 30;
        if (j >= BINS) { j -= BINS; cc += 1; }
    }
}

extern "C" void kernel_launch(void* const* d_in, const int* in_sizes, int n_in,
                              void* d_out, int out_size) {
    const float* fm        = (const float*)d_in[0];
    const float* proposals = (const float*)d_in[1];
    float* out = (float*)d_out;

    transpose_kernel<<<dim3((FH * FW + 31) / 32, NCH / 32), dim3(32, 8)>>>(fm);
    roialign_kernel<<<2 * NPROP, 128>>>(proposals, out);
}

// round 7
// speedup vs baseline: 1.2088x; 1.0517x over previous
#include <cuda_runtime.h>

#define NCH   256
#define FH    50
#define FW    50
#define NPROP 1024
#define OUTS  7
#define NS    14          // OUTS*SRATE
#define BINS  49
#define HALF  128         // channels per staging pass
#define HALF_ELEMS (HALF*BINS)    // 6272
#define HALF_V4   (HALF_ELEMS/4)  // 1568
#define OUT_PER_PROP (NCH*BINS)   // 12544

// fm transposed to [y][x][c] so channel gathers are coalesced
__device__ float g_fmT[FH * FW * NCH];

// ---------------- Kernel 1: (C,H,W) -> (H,W,C) transpose ----------------
__global__ void transpose_kernel(const float* __restrict__ fm) {
    __shared__ float tile[32][33];
    const int P = FH * FW;               // 2500
    int pTile = blockIdx.x * 32;
    int cTile = blockIdx.y * 32;
    int tx = threadIdx.x, ty = threadIdx.y;

    int p = pTile + tx;
    #pragma unroll
    for (int i = 0; i < 32; i += 8) {
        int c = cTile + ty + i;
        if (p < P) tile[ty + i][tx] = fm[c * P + p];
    }
    __syncthreads();
    int c2 = cTile + tx;
    #pragma unroll
    for (int i = 0; i < 32; i += 8) {
        int pp = pTile + ty + i;
        if (pp < P) g_fmT[pp * NCH + c2] = tile[tx][ty + i];
    }
}

// ---------------- Kernel 2: ROI Align, one proposal per block ----------------
__global__ __launch_bounds__(128) void roialign_kernel(
    const float* __restrict__ proposals, float* __restrict__ out)
{
    const int n = blockIdx.x;
    const int t = threadIdx.x;           // 0..127

    __shared__ int   sx0[NS], sx1[NS], sy0[NS], sy1[NS];
    __shared__ float swx0[NS], swx1[NS], swy0[NS], swy1[NS];
    __shared__ float WX[OUTS][4], WY[OUTS][4];
    // output-linear staging: stage[c_local*49 + j]  (25,088 B -> 8 blocks/SM)
    __shared__ __align__(16) float stage[HALF_ELEMS];

    // ---- per-axis per-sample interpolation tables (28 threads) ----
    if (t < 2 * NS) {
        const int axis = t / NS;         // 0 = x, 1 = y
        const int s    = t % NS;
        const float SC = 1.0f / 16.0f;
        float lo = proposals[n * 4 + (axis == 0 ? 0 : 1)] * SC * SC;
        float hi = proposals[n * 4 + (axis == 0 ? 2 : 3)] * SC * SC;
        float roi   = fmaxf(hi - lo, 1.0f);
        float binsz = roi * (1.0f / OUTS);
        float gv    = ((float)s + 0.5f) * 0.5f;
        float v     = lo + binsz * gv;
        const float Lf = 50.0f;
        bool valid = (v >= -1.0f) && (v <= Lf);
        float vc = fminf(fmaxf(v, 0.0f), Lf - 1.0f);
        int i0 = min((int)floorf(vc), 49);
        int i1 = min(i0 + 1, 49);
        float l = vc - (float)i0;
        float h = 1.0f - l;
        if (!valid) { h = 0.0f; l = 0.0f; }
        if (axis == 0) { sx0[s] = i0; sx1[s] = i1; swx0[s] = h; swx1[s] = l; }
        else           { sy0[s] = i0; sy1[s] = i1; swy0[s] = h; swy1[s] = l; }
    }
    __syncthreads();

    const int xb = sx0[0], yb = sy0[0];
    const int xspan = sx1[NS - 1] - xb;
    const int yspan = sy1[NS - 1] - yb;
    const bool fast = (xspan <= 2) && (yspan <= 2);

    // ---- aggregate bin weights WX/WY (14 threads); 0.25 bin-avg folded in ----
    if (t < 2 * OUTS) {
        const int axis = t / OUTS;
        const int b    = t % OUTS;
        float w0 = 0.f, w1 = 0.f, w2 = 0.f;
        #pragma unroll
        for (int d = 0; d < 2; d++) {
            int s = 2 * b + d;
            int r0, r1; float a, c;
            if (axis == 0) { r0 = sx0[s] - xb; r1 = sx1[s] - xb; a = swx0[s]; c = swx1[s]; }
            else           { r0 = sy0[s] - yb; r1 = sy1[s] - yb; a = swy0[s]; c = swy1[s]; }
            if ((unsigned)r0 < 3u) { if (r0 == 0) w0 += a; else if (r0 == 1) w1 += a; else w2 += a; }
            if ((unsigned)r1 < 3u) { if (r1 == 0) w0 += c; else if (r1 == 1) w1 += c; else w2 += c; }
        }
        const float q = 0.5f;            // 0.5*0.5 = 0.25 bin average
        if (axis == 0) { WX[b][0] = w0*q; WX[b][1] = w1*q; WX[b][2] = w2*q; }
        else           { WY[b][0] = w0*q; WY[b][1] = w1*q; WY[b][2] = w2*q; }
    }
    __syncthreads();

    // ---- two staging passes of 128 channels each ----
    #pragma unroll
    for (int half = 0; half < 2; half++) {
        const int c = t + half * HALF;
        float* srow = &stage[t * BINS];  // thread-private 49-float row

        if (fast) {
            float b9[3][3];
            #pragma unroll
            for (int ty = 0; ty < 3; ty++) {
                int yy = min(yb + ty, FH - 1);
                #pragma unroll
                for (int tx = 0; tx < 3; tx++) {
                    int xx = min(xb + tx, FW - 1);
                    b9[ty][tx] = g_fmT[(yy * FW + xx) * NCH + c];
                }
            }
            #pragma unroll
            for (int by = 0; by < OUTS; by++) {
                float wy0 = WY[by][0], wy1 = WY[by][1], wy2 = WY[by][2];
                float t0 = wy0 * b9[0][0] + wy1 * b9[1][0] + wy2 * b9[2][0];
                float t1 = wy0 * b9[0][1] + wy1 * b9[1][1] + wy2 * b9[2][1];
                float t2 = wy0 * b9[0][2] + wy1 * b9[1][2] + wy2 * b9[2][2];
                #pragma unroll
                for (int bx = 0; bx < OUTS; bx++) {
                    srow[by * OUTS + bx] =
                        WX[bx][0] * t0 + WX[bx][1] * t1 + WX[bx][2] * t2;
                }
            }
        } else {
            // general fallback: literal per-sample bilinear gather
            for (int j = 0; j < BINS; j++) {
                int by = j / OUTS, bx = j - by * OUTS;
                float a0 = 0.f;
                #pragma unroll
                for (int dy = 0; dy < 2; dy++) {
                    int sy = 2 * by + dy;
                    const float* r0 = &g_fmT[sy0[sy] * FW * NCH];
                    const float* r1 = &g_fmT[sy1[sy] * FW * NCH];
                    float hy = swy0[sy], ly = swy1[sy];
                    #pragma unroll
                    for (int dx = 0; dx < 2; dx++) {
                        int sx = 2 * bx + dx;
                        int o0 = sx0[sx] * NCH, o1 = sx1[sx] * NCH;
                        float hx = swx0[sx], lx = swx1[sx];
                        a0 += hy * (hx * r0[o0 + c] + lx * r0[o1 + c])
                            + ly * (hx * r1[o0 + c] + lx * r1[o1 + c]);
                    }
                }
                srow[j] = 0.25f * a0;
            }
        }
        __syncthreads();

        // ---- vectorized linear writeback: stage is already output-ordered ----
        const float4* s4 = (const float4*)stage;
        float4* o4 = (float4*)(out + (size_t)n * OUT_PER_PROP
                                   + (size_t)half * HALF_ELEMS);
        #pragma unroll 4
        for (int i = t; i < HALF_V4; i += 128) {
            o4[i] = s4[i];
        }
        __syncthreads();
    }
}

extern "C" void kernel_launch(void* const* d_in, const int* in_sizes, int n_in,
                              void* d_out, int out_size) {
    const float* fm        = (const float*)d_in[0];
    const float* proposals = (const float*)d_in[1];
    float* out = (float*)d_out;

    transpose_kernel<<<dim3((FH * FW + 31) / 32, NCH / 32), dim3(32, 8)>>>(fm);
    roialign_kernel<<<NPROP, 128>>>(proposals, out);
}